// round 4
// baseline (speedup 1.0000x reference)
#include <cuda_runtime.h>
#include <cuda_bf16.h>
#include <math.h>

// Problem constants
#define BB 2
#define SS 2048
#define DD 768
#define HH 12
#define DH 64
#define TT 64
#define RR 50
#define FFD 3072

// ---------------- scratch (device globals; no allocation allowed) ----------------
__device__ float g_q  [BB*SS*DD];
__device__ float g_k  [BB*SS*DD];
__device__ float g_v  [BB*SS*DD];
__device__ float g_ctx[BB*SS*DD];
__device__ float g_t1 [BB*SS*DD];
__device__ float g_t2 [BB*SS*DD];
__device__ float g_ff [BB*SS*FFD];
__device__ float g_tagk[TT*DD];
__device__ float g_tagv[TT*DD];

// ---------------- GEMM: C[M,N] = A[M,K] @ W[K,N] + bias, optional exact GELU ----------------
// 128x128 tile, BK=8, 256 threads, 8x8 microtile per thread.
// Requires: K % 8 == 0, N % 128 == 0. M guarded.
__global__ __launch_bounds__(256) void gemm_kernel(
    const float* __restrict__ A, const float* __restrict__ W,
    const float* __restrict__ bias, float* __restrict__ C,
    int M, int N, int K, int act)
{
    __shared__ float As[8][128];
    __shared__ float Bs[8][128];

    const int bm = blockIdx.y * 128;
    const int bn = blockIdx.x * 128;
    const int tid = threadIdx.x;
    const int ty = tid >> 4;        // 0..15
    const int tx = tid & 15;        // 0..15

    float acc[8][8];
#pragma unroll
    for (int i = 0; i < 8; i++)
#pragma unroll
        for (int j = 0; j < 8; j++) acc[i][j] = 0.f;

    const int a_row  = tid >> 1;          // 0..127
    const int a_col4 = (tid & 1) * 4;     // 0 or 4
    const int b_row  = tid >> 5;          // 0..7
    const int b_col4 = (tid & 31) * 4;    // 0..124

    for (int k0 = 0; k0 < K; k0 += 8) {
        float4 av = make_float4(0.f, 0.f, 0.f, 0.f);
        int gm = bm + a_row;
        if (gm < M) av = *(const float4*)&A[(size_t)gm * K + k0 + a_col4];
        As[a_col4 + 0][a_row] = av.x;
        As[a_col4 + 1][a_row] = av.y;
        As[a_col4 + 2][a_row] = av.z;
        As[a_col4 + 3][a_row] = av.w;

        float4 bv = *(const float4*)&W[(size_t)(k0 + b_row) * N + bn + b_col4];
        *(float4*)&Bs[b_row][b_col4] = bv;

        __syncthreads();

#pragma unroll
        for (int kk = 0; kk < 8; kk++) {
            float ar[8], br[8];
            float4 a0 = *(const float4*)&As[kk][ty * 8];
            float4 a1 = *(const float4*)&As[kk][ty * 8 + 4];
            ar[0]=a0.x; ar[1]=a0.y; ar[2]=a0.z; ar[3]=a0.w;
            ar[4]=a1.x; ar[5]=a1.y; ar[6]=a1.z; ar[7]=a1.w;
            float4 b0 = *(const float4*)&Bs[kk][tx * 8];
            float4 b1 = *(const float4*)&Bs[kk][tx * 8 + 4];
            br[0]=b0.x; br[1]=b0.y; br[2]=b0.z; br[3]=b0.w;
            br[4]=b1.x; br[5]=b1.y; br[6]=b1.z; br[7]=b1.w;
#pragma unroll
            for (int i = 0; i < 8; i++)
#pragma unroll
                for (int j = 0; j < 8; j++)
                    acc[i][j] += ar[i] * br[j];
        }
        __syncthreads();
    }

    // epilogue
#pragma unroll
    for (int i = 0; i < 8; i++) {
        int m = bm + ty * 8 + i;
        if (m >= M) break;
#pragma unroll
        for (int j = 0; j < 8; j++) {
            int n = bn + tx * 8 + j;
            float val = acc[i][j] + bias[n];
            if (act == 1) {
                // exact erf GELU
                val = 0.5f * val * (1.f + erff(val * 0.70710678118654752440f));
            }
            C[(size_t)m * N + n] = val;
        }
    }
}

// ---------------- Flash attention (online softmax, additive band mask) ----------------
// Grid: (Sq/64, H, B), 256 threads. Each query handled by 4 consecutive lanes;
// lane c owns dims [c*16, c*16+16) of the output. Keys processed in groups of 4:
// lane c computes the full 64-dim dot for key j0+c (1 exp per (q,key)).
__global__ __launch_bounds__(256) void attn_kernel(
    const float* __restrict__ Q, const float* __restrict__ Kg, const float* __restrict__ Vg,
    float* __restrict__ O, int Sq, int Sk, long kvbs, int bandR)
{
    __shared__ float Ks[64][68];
    __shared__ float Vs[64][68];

    const int b = blockIdx.z, h = blockIdx.y;
    const int tid = threadIdx.x;
    const int ql = tid >> 2;   // 0..63
    const int c  = tid & 3;    // 0..3
    const int qg = blockIdx.x * 64 + ql;
    const int lane = tid & 31;
    const int gbase = lane & ~3;
    const unsigned fm = 0xFFFFFFFFu;

    const float* qptr = Q + ((size_t)b * Sq + qg) * DD + h * DH;
    float qr[64];
#pragma unroll
    for (int i = 0; i < 64; i += 4) {
        float4 t = *(const float4*)(qptr + i);
        qr[i] = t.x; qr[i+1] = t.y; qr[i+2] = t.z; qr[i+3] = t.w;
    }

    float acc[16];
#pragma unroll
    for (int i = 0; i < 16; i++) acc[i] = 0.f;
    float mv = -3.0e38f, lv = 0.f;

    for (int k0 = 0; k0 < Sk; k0 += 64) {
        __syncthreads();
        // cooperative load of K/V tile: 64 rows x 64 cols (as 1024 float4 each)
        for (int i = tid; i < 1024; i += 256) {
            int r  = i >> 4;
            int cc = (i & 15) << 2;
            size_t base = (size_t)b * kvbs + (size_t)(k0 + r) * DD + h * DH + cc;
            *(float4*)&Ks[r][cc] = *(const float4*)&Kg[base];
            *(float4*)&Vs[r][cc] = *(const float4*)&Vg[base];
        }
        __syncthreads();

        for (int j0 = 0; j0 < 64; j0 += 4) {
            const int j = j0 + c;
            float s = 0.f;
#pragma unroll
            for (int kk = 0; kk < 64; kk += 4) {
                float4 k4 = *(const float4*)&Ks[j][kk];
                s += qr[kk] * k4.x + qr[kk+1] * k4.y + qr[kk+2] * k4.z + qr[kk+3] * k4.w;
            }
            s *= 0.125f;  // 1/sqrt(64)
            if (bandR >= 0) {
                int kgl = k0 + j;
                int d = qg - kgl;
                if (d < 0) d = -d;
                s += (d <= bandR) ? 1.f : 0.f;
            }
            // max over the 4 lanes of this query
            float gm = s;
            gm = fmaxf(gm, __shfl_xor_sync(fm, gm, 1));
            gm = fmaxf(gm, __shfl_xor_sync(fm, gm, 2));
            float m_new = fmaxf(mv, gm);
            float scale = __expf(mv - m_new);
            float p = __expf(s - m_new);
            float ps0 = __shfl_sync(fm, p, gbase + 0);
            float ps1 = __shfl_sync(fm, p, gbase + 1);
            float ps2 = __shfl_sync(fm, p, gbase + 2);
            float ps3 = __shfl_sync(fm, p, gbase + 3);
            lv = lv * scale + (ps0 + ps1 + ps2 + ps3);
#pragma unroll
            for (int i = 0; i < 16; i++) acc[i] *= scale;

            const float* v0 = &Vs[j0 + 0][c * 16];
            const float* v1 = &Vs[j0 + 1][c * 16];
            const float* v2 = &Vs[j0 + 2][c * 16];
            const float* v3 = &Vs[j0 + 3][c * 16];
#pragma unroll
            for (int i = 0; i < 16; i += 4) {
                float4 a0 = *(const float4*)&v0[i];
                float4 a1 = *(const float4*)&v1[i];
                float4 a2 = *(const float4*)&v2[i];
                float4 a3 = *(const float4*)&v3[i];
                acc[i+0] += ps0*a0.x + ps1*a1.x + ps2*a2.x + ps3*a3.x;
                acc[i+1] += ps0*a0.y + ps1*a1.y + ps2*a2.y + ps3*a3.y;
                acc[i+2] += ps0*a0.z + ps1*a1.z + ps2*a2.z + ps3*a3.z;
                acc[i+3] += ps0*a0.w + ps1*a1.w + ps2*a2.w + ps3*a3.w;
            }
            mv = m_new;
        }
    }

    float inv = 1.f / lv;
    float* optr = O + ((size_t)b * Sq + qg) * DD + h * DH + c * 16;
#pragma unroll
    for (int i = 0; i < 16; i += 4) {
        float4 o4;
        o4.x = acc[i+0]*inv; o4.y = acc[i+1]*inv; o4.z = acc[i+2]*inv; o4.w = acc[i+3]*inv;
        *(float4*)&optr[i] = o4;
    }
}

// ---------------- bias-residual-LayerNorm (X already has bias; add residual, LN) ----------------
__global__ __launch_bounds__(256) void ln_kernel(
    const float* __restrict__ X, const float* __restrict__ Res,
    const float* __restrict__ g, const float* __restrict__ bb,
    float* __restrict__ out)
{
    __shared__ float red[256];
    const int row = blockIdx.x;
    const int tid = threadIdx.x;
    const size_t base = (size_t)row * DD;

    float v0 = X[base + tid]       + Res[base + tid];
    float v1 = X[base + tid + 256] + Res[base + tid + 256];
    float v2 = X[base + tid + 512] + Res[base + tid + 512];

    red[tid] = v0 + v1 + v2;
    __syncthreads();
    for (int s = 128; s > 0; s >>= 1) {
        if (tid < s) red[tid] += red[tid + s];
        __syncthreads();
    }
    float mean = red[0] * (1.f / DD);
    __syncthreads();

    float d0 = v0 - mean, d1 = v1 - mean, d2 = v2 - mean;
    red[tid] = d0*d0 + d1*d1 + d2*d2;
    __syncthreads();
    for (int s = 128; s > 0; s >>= 1) {
        if (tid < s) red[tid] += red[tid + s];
        __syncthreads();
    }
    float inv = rsqrtf(red[0] * (1.f / DD) + 1e-12f);

    out[base + tid]       = d0 * inv * g[tid]       + bb[tid];
    out[base + tid + 256] = d1 * inv * g[tid + 256] + bb[tid + 256];
    out[base + tid + 512] = d2 * inv * g[tid + 512] + bb[tid + 512];
}

// ---------------- launch ----------------
static void launch_gemm(const float* A, const float* W, const float* bias, float* C,
                        int M, int N, int K, int act)
{
    dim3 grid((N + 127) / 128, (M + 127) / 128);
    gemm_kernel<<<grid, 256>>>(A, W, bias, C, M, N, K, act);
}

extern "C" void kernel_launch(void* const* d_in, const int* in_sizes, int n_in,
                              void* d_out, int out_size)
{
    const float* hs      = (const float*)d_in[0];
    const float* tag_emb = (const float*)d_in[1];
    const float* sa_wq = (const float*)d_in[2];  const float* sa_bq = (const float*)d_in[3];
    const float* sa_wk = (const float*)d_in[4];  const float* sa_bk = (const float*)d_in[5];
    const float* sa_wv = (const float*)d_in[6];  const float* sa_bv = (const float*)d_in[7];
    const float* sa_wo = (const float*)d_in[8];  const float* sa_bo = (const float*)d_in[9];
    const float* sa_ln_g = (const float*)d_in[10]; const float* sa_ln_b = (const float*)d_in[11];
    const float* ca_wq = (const float*)d_in[12]; const float* ca_bq = (const float*)d_in[13];
    const float* ca_wk = (const float*)d_in[14]; const float* ca_bk = (const float*)d_in[15];
    const float* ca_wv = (const float*)d_in[16]; const float* ca_bv = (const float*)d_in[17];
    const float* ca_wo = (const float*)d_in[18]; const float* ca_bo = (const float*)d_in[19];
    const float* ca_ln_g = (const float*)d_in[20]; const float* ca_ln_b = (const float*)d_in[21];
    const float* ff_w1 = (const float*)d_in[22]; const float* ff_b1 = (const float*)d_in[23];
    const float* ff_w2 = (const float*)d_in[24]; const float* ff_b2 = (const float*)d_in[25];
    const float* ff_ln_g = (const float*)d_in[26]; const float* ff_ln_b = (const float*)d_in[27];

    float* out = (float*)d_out;

    float *q, *k, *v, *ctx, *t1, *t2, *ff, *tk, *tv;
    cudaGetSymbolAddress((void**)&q,   g_q);
    cudaGetSymbolAddress((void**)&k,   g_k);
    cudaGetSymbolAddress((void**)&v,   g_v);
    cudaGetSymbolAddress((void**)&ctx, g_ctx);
    cudaGetSymbolAddress((void**)&t1,  g_t1);
    cudaGetSymbolAddress((void**)&t2,  g_t2);
    cudaGetSymbolAddress((void**)&ff,  g_ff);
    cudaGetSymbolAddress((void**)&tk,  g_tagk);
    cudaGetSymbolAddress((void**)&tv,  g_tagv);

    const int M = BB * SS;  // 4096

    // ---- self attention ----
    launch_gemm(hs, sa_wq, sa_bq, q, M, DD, DD, 0);
    launch_gemm(hs, sa_wk, sa_bk, k, M, DD, DD, 0);
    launch_gemm(hs, sa_wv, sa_bv, v, M, DD, DD, 0);

    attn_kernel<<<dim3(SS / 64, HH, BB), 256>>>(q, k, v, ctx, SS, SS, (long)SS * DD, RR);

    launch_gemm(ctx, sa_wo, sa_bo, v, M, DD, DD, 0);
    ln_kernel<<<M, 256>>>(v, hs, sa_ln_g, sa_ln_b, t1);

    // ---- cross attention over tag embeddings ----
    launch_gemm(tag_emb, ca_wk, ca_bk, tk, TT, DD, DD, 0);
    launch_gemm(tag_emb, ca_wv, ca_bv, tv, TT, DD, DD, 0);
    launch_gemm(t1, ca_wq, ca_bq, q, M, DD, DD, 0);

    attn_kernel<<<dim3(SS / 64, HH, BB), 256>>>(q, tk, tv, ctx, SS, TT, 0L, -1);

    launch_gemm(ctx, ca_wo, ca_bo, v, M, DD, DD, 0);
    ln_kernel<<<M, 256>>>(v, t1, ca_ln_g, ca_ln_b, t2);

    // ---- FFN ----
    launch_gemm(t2, ff_w1, ff_b1, ff, M, FFD, DD, 1);     // fused exact GELU
    launch_gemm(ff, ff_w2, ff_b2, q, M, DD, FFD, 0);
    ln_kernel<<<M, 256>>>(q, t2, ff_ln_g, ff_ln_b, out);
}

// round 8
// speedup vs baseline: 1.4836x; 1.4836x over previous
#include <cuda_runtime.h>
#include <cuda_bf16.h>
#include <math.h>
#include <stdint.h>

// Problem constants
#define BB 2
#define SS 2048
#define DD 768
#define HH 12
#define DH 64
#define TT 64
#define RR 50
#define FFD 3072

// ---------------- scratch (device globals; no allocation allowed) ----------------
__device__ float g_q  [BB*SS*DD];
__device__ float g_k  [BB*SS*DD];
__device__ float g_v  [BB*SS*DD];
__device__ float g_ctx[BB*SS*DD];
__device__ float g_t1 [BB*SS*DD];
__device__ float g_t2 [BB*SS*DD];
__device__ float g_ff [BB*SS*FFD];
__device__ float g_tagk[TT*DD];
__device__ float g_tagv[TT*DD];

// ================= PTX helpers (portable PTX only: ldmatrix + mma.sync) =================
__device__ __forceinline__ uint32_t smem_u32(const void* p) {
    uint32_t a;
    asm("{ .reg .u64 t; cvta.to.shared.u64 t, %1; cvt.u32.u64 %0, t; }" : "=r"(a) : "l"(p));
    return a;
}
__device__ __forceinline__ void ldsm_x4(uint32_t* r, uint32_t addr) {
    asm volatile("ldmatrix.sync.aligned.m8n8.x4.shared.b16 {%0,%1,%2,%3}, [%4];"
                 : "=r"(r[0]), "=r"(r[1]), "=r"(r[2]), "=r"(r[3]) : "r"(addr));
}
__device__ __forceinline__ void ldsm_x4_t(uint32_t* r, uint32_t addr) {
    asm volatile("ldmatrix.sync.aligned.m8n8.x4.trans.shared.b16 {%0,%1,%2,%3}, [%4];"
                 : "=r"(r[0]), "=r"(r[1]), "=r"(r[2]), "=r"(r[3]) : "r"(addr));
}
__device__ __forceinline__ void mma_bf16(float* d, const uint32_t* a, const uint32_t* b) {
    asm volatile(
        "mma.sync.aligned.m16n8k16.row.col.f32.bf16.bf16.f32 "
        "{%0,%1,%2,%3}, {%4,%5,%6,%7}, {%8,%9}, {%0,%1,%2,%3};"
        : "+f"(d[0]), "+f"(d[1]), "+f"(d[2]), "+f"(d[3])
        : "r"(a[0]), "r"(a[1]), "r"(a[2]), "r"(a[3]), "r"(b[0]), "r"(b[1]));
}

// pack two floats into bf16x2 hi and lo (error) words
__device__ __forceinline__ void split2(float x, float y, uint32_t& hi, uint32_t& lo) {
    __nv_bfloat16 h0 = __float2bfloat16(x);
    __nv_bfloat16 h1 = __float2bfloat16(y);
    __nv_bfloat16 e0 = __float2bfloat16(x - __bfloat162float(h0));
    __nv_bfloat16 e1 = __float2bfloat16(y - __bfloat162float(h1));
    hi = (uint32_t)__bfloat16_as_ushort(h0) | ((uint32_t)__bfloat16_as_ushort(h1) << 16);
    lo = (uint32_t)__bfloat16_as_ushort(e0) | ((uint32_t)__bfloat16_as_ushort(e1) << 16);
}

// ================= HMMA GEMM =================
// C[M,N] = A[M,K](fp32) @ W[K,N](fp32) + bias, optional exact GELU.
// CTA: 128x128 tile, BK=32. 8 warps in 4(m) x 2(n); warp tile 32x64.
// 3-term bf16 split: AhiBhi + AloBhi + AhiBlo (fp32 accum) -> ~fp32 accuracy.
// A smem: [m][k] bf16, row stride 40 bf16 (80B: 16B-aligned, conflict-free ldmatrix).
// B smem: [k][n] bf16, row stride 128 bf16 (256B) with 16B-granule XOR swizzle.
// Requires N % 128 == 0, K % 32 == 0. M guarded.
#define A_RS 80     // bytes per A smem row
#define B_RS 256    // bytes per B smem row

__global__ __launch_bounds__(256, 2)
void gemm_tc_kernel(const float* __restrict__ A, const float* __restrict__ W,
                    const float* __restrict__ bias, float* __restrict__ C,
                    int M, int N, int K, int act)
{
    __shared__ __align__(16) unsigned char sAhi[128 * A_RS];
    __shared__ __align__(16) unsigned char sAlo[128 * A_RS];
    __shared__ __align__(16) unsigned char sBhi[32 * B_RS];
    __shared__ __align__(16) unsigned char sBlo[32 * B_RS];

    const int tid  = threadIdx.x;
    const int lane = tid & 31;
    const int wid  = tid >> 5;
    const int wm   = (wid & 3) * 32;   // warp m offset in tile
    const int wn   = (wid >> 2) * 64;  // warp n offset in tile
    const int bm   = blockIdx.y * 128;
    const int bn   = blockIdx.x * 128;

    const uint32_t aHiB = smem_u32(sAhi);
    const uint32_t aLoB = smem_u32(sAlo);
    const uint32_t bHiB = smem_u32(sBhi);
    const uint32_t bLoB = smem_u32(sBlo);

    float acc[2][8][4];
#pragma unroll
    for (int mt = 0; mt < 2; mt++)
#pragma unroll
        for (int nt = 0; nt < 8; nt++)
#pragma unroll
            for (int j = 0; j < 4; j++) acc[mt][nt][j] = 0.f;

    // ---- loader mappings ----
    const int a_row = tid >> 1;             // 0..127
    const int a_k   = (tid & 1) * 16;       // 0 / 16
    const bool a_ok = (bm + a_row) < M;
    const float* ap = A + (size_t)(bm + a_row) * K + a_k;
    const uint32_t a_st = a_row * A_RS + a_k * 2;

    const int b_row = tid >> 3;             // 0..31
    const int b_n4  = (tid & 7) * 4;        // n start; +32 per iter
    const float* wp = W + (size_t)b_row * N + bn + b_n4;
    const int b_swz_st = (b_row & 7) << 4;

    // ---- fragment address components ----
    // A ldmatrix.x4: row = wm + mt*16 + (lane&15), k-half = (lane>>4)*8
    const uint32_t a_fr = (uint32_t)((wm + (lane & 15)) * A_RS + (lane >> 4) * 16);
    // B ldmatrix.x4.trans: row = klocal + (lane&7) + ((lane>>3)&1)*8, col = n0 + (lane>>4)*8
    const int b_rb  = (lane & 7) + ((lane >> 3) & 1) * 8;
    const int b_swz = (lane & 7) << 4;
    uint32_t b_col2[4];
#pragma unroll
    for (int p = 0; p < 4; p++)
        b_col2[p] = (uint32_t)(((wn + p * 16 + (lane >> 4) * 8) * 2) ^ b_swz);

    const int nchunks = K >> 5;
    for (int kc = 0; kc < nchunks; kc++) {
        const int k0 = kc << 5;
        __syncthreads();   // previous chunk's mma reads done before overwrite

        // ---- A tile: 128 x 32 fp32 -> bf16 hi/lo ----
#pragma unroll
        for (int i = 0; i < 4; i++) {
            float4 v = make_float4(0.f, 0.f, 0.f, 0.f);
            if (a_ok) v = *(const float4*)(ap + k0 + i * 4);
            uint2 hv, lv;
            split2(v.x, v.y, hv.x, lv.x);
            split2(v.z, v.w, hv.y, lv.y);
            uint32_t off = a_st + i * 8;
            *(uint2*)(sAhi + off) = hv;
            *(uint2*)(sAlo + off) = lv;
        }
        // ---- B tile: 32 x 128 fp32 -> bf16 hi/lo, [k][n], swizzled ----
#pragma unroll
        for (int i = 0; i < 4; i++) {
            float4 v = *(const float4*)(wp + (size_t)k0 * N + i * 32);
            uint2 hv, lv;
            split2(v.x, v.y, hv.x, lv.x);
            split2(v.z, v.w, hv.y, lv.y);
            uint32_t off = b_row * B_RS + ((uint32_t)((b_n4 + i * 32) * 2) ^ b_swz_st);
            *(uint2*)(sBhi + off) = hv;
            *(uint2*)(sBlo + off) = lv;
        }
        __syncthreads();

        // ---- compute: 2 k-steps of 16 ----
#pragma unroll
        for (int ks = 0; ks < 2; ks++) {
            const uint32_t klb = ks * 32;         // byte offset of k-step in A rows
            const uint32_t krb = (ks * 16) * B_RS; // row-byte offset in B

            uint32_t ahi[2][4];
            ldsm_x4(ahi[0], aHiB + a_fr + klb);
            ldsm_x4(ahi[1], aHiB + a_fr + 16 * A_RS + klb);

            uint32_t bf[8][2];
#pragma unroll
            for (int p = 0; p < 4; p++) {
                uint32_t r[4];
                ldsm_x4_t(r, bHiB + krb + (uint32_t)(b_rb * B_RS) + b_col2[p]);
                bf[2*p][0] = r[0]; bf[2*p][1] = r[1];
                bf[2*p+1][0] = r[2]; bf[2*p+1][1] = r[3];
            }
            // term 1: Ahi * Bhi
#pragma unroll
            for (int mt = 0; mt < 2; mt++)
#pragma unroll
                for (int nt = 0; nt < 8; nt++)
                    mma_bf16(acc[mt][nt], ahi[mt], bf[nt]);

            // term 2: Alo * Bhi
            uint32_t alo[2][4];
            ldsm_x4(alo[0], aLoB + a_fr + klb);
            ldsm_x4(alo[1], aLoB + a_fr + 16 * A_RS + klb);
#pragma unroll
            for (int mt = 0; mt < 2; mt++)
#pragma unroll
                for (int nt = 0; nt < 8; nt++)
                    mma_bf16(acc[mt][nt], alo[mt], bf[nt]);

            // term 3: Ahi * Blo (reuse bf regs)
#pragma unroll
            for (int p = 0; p < 4; p++) {
                uint32_t r[4];
                ldsm_x4_t(r, bLoB + krb + (uint32_t)(b_rb * B_RS) + b_col2[p]);
                bf[2*p][0] = r[0]; bf[2*p][1] = r[1];
                bf[2*p+1][0] = r[2]; bf[2*p+1][1] = r[3];
            }
#pragma unroll
            for (int mt = 0; mt < 2; mt++)
#pragma unroll
                for (int nt = 0; nt < 8; nt++)
                    mma_bf16(acc[mt][nt], ahi[mt], bf[nt]);
        }
    }

    // ---- epilogue: bias (+ exact GELU), direct global stores ----
    const int r0 = bm + wm + (lane >> 2);
    const int cbase = bn + wn + (lane & 3) * 2;
#pragma unroll
    for (int mt = 0; mt < 2; mt++) {
#pragma unroll
        for (int half = 0; half < 2; half++) {
            const int row = r0 + mt * 16 + half * 8;
            if (row >= M) continue;
#pragma unroll
            for (int nt = 0; nt < 8; nt++) {
                const int col = cbase + nt * 8;
                float d0 = acc[mt][nt][half * 2 + 0] + bias[col];
                float d1 = acc[mt][nt][half * 2 + 1] + bias[col + 1];
                if (act == 1) {
                    d0 = 0.5f * d0 * (1.f + erff(d0 * 0.70710678118654752440f));
                    d1 = 0.5f * d1 * (1.f + erff(d1 * 0.70710678118654752440f));
                }
                *(float2*)&C[(size_t)row * N + col] = make_float2(d0, d1);
            }
        }
    }
}

// ---------------- Flash attention (online softmax, additive band mask) ----------------
__global__ __launch_bounds__(256) void attn_kernel(
    const float* __restrict__ Q, const float* __restrict__ Kg, const float* __restrict__ Vg,
    float* __restrict__ O, int Sq, int Sk, long kvbs, int bandR)
{
    __shared__ float Ks[64][68];
    __shared__ float Vs[64][68];

    const int b = blockIdx.z, h = blockIdx.y;
    const int tid = threadIdx.x;
    const int ql = tid >> 2;   // 0..63
    const int c  = tid & 3;    // 0..3
    const int qg = blockIdx.x * 64 + ql;
    const int lane = tid & 31;
    const int gbase = lane & ~3;
    const unsigned fm = 0xFFFFFFFFu;

    const float* qptr = Q + ((size_t)b * Sq + qg) * DD + h * DH;
    float qr[64];
#pragma unroll
    for (int i = 0; i < 64; i += 4) {
        float4 t = *(const float4*)(qptr + i);
        qr[i] = t.x; qr[i+1] = t.y; qr[i+2] = t.z; qr[i+3] = t.w;
    }

    float acc[16];
#pragma unroll
    for (int i = 0; i < 16; i++) acc[i] = 0.f;
    float mv = -3.0e38f, lv = 0.f;

    for (int k0 = 0; k0 < Sk; k0 += 64) {
        __syncthreads();
        for (int i = tid; i < 1024; i += 256) {
            int r  = i >> 4;
            int cc = (i & 15) << 2;
            size_t base = (size_t)b * kvbs + (size_t)(k0 + r) * DD + h * DH + cc;
            *(float4*)&Ks[r][cc] = *(const float4*)&Kg[base];
            *(float4*)&Vs[r][cc] = *(const float4*)&Vg[base];
        }
        __syncthreads();

        for (int j0 = 0; j0 < 64; j0 += 4) {
            const int j = j0 + c;
            float s = 0.f;
#pragma unroll
            for (int kk = 0; kk < 64; kk += 4) {
                float4 k4 = *(const float4*)&Ks[j][kk];
                s += qr[kk] * k4.x + qr[kk+1] * k4.y + qr[kk+2] * k4.z + qr[kk+3] * k4.w;
            }
            s *= 0.125f;
            if (bandR >= 0) {
                int kgl = k0 + j;
                int d = qg - kgl;
                if (d < 0) d = -d;
                s += (d <= bandR) ? 1.f : 0.f;
            }
            float gm = s;
            gm = fmaxf(gm, __shfl_xor_sync(fm, gm, 1));
            gm = fmaxf(gm, __shfl_xor_sync(fm, gm, 2));
            float m_new = fmaxf(mv, gm);
            float scale = __expf(mv - m_new);
            float p = __expf(s - m_new);
            float ps0 = __shfl_sync(fm, p, gbase + 0);
            float ps1 = __shfl_sync(fm, p, gbase + 1);
            float ps2 = __shfl_sync(fm, p, gbase + 2);
            float ps3 = __shfl_sync(fm, p, gbase + 3);
            lv = lv * scale + (ps0 + ps1 + ps2 + ps3);
#pragma unroll
            for (int i = 0; i < 16; i++) acc[i] *= scale;

            const float* v0 = &Vs[j0 + 0][c * 16];
            const float* v1 = &Vs[j0 + 1][c * 16];
            const float* v2 = &Vs[j0 + 2][c * 16];
            const float* v3 = &Vs[j0 + 3][c * 16];
#pragma unroll
            for (int i = 0; i < 16; i += 4) {
                float4 a0 = *(const float4*)&v0[i];
                float4 a1 = *(const float4*)&v1[i];
                float4 a2 = *(const float4*)&v2[i];
                float4 a3 = *(const float4*)&v3[i];
                acc[i+0] += ps0*a0.x + ps1*a1.x + ps2*a2.x + ps3*a3.x;
                acc[i+1] += ps0*a0.y + ps1*a1.y + ps2*a2.y + ps3*a3.y;
                acc[i+2] += ps0*a0.z + ps1*a1.z + ps2*a2.z + ps3*a3.z;
                acc[i+3] += ps0*a0.w + ps1*a1.w + ps2*a2.w + ps3*a3.w;
            }
            mv = m_new;
        }
    }

    float inv = 1.f / lv;
    float* optr = O + ((size_t)b * Sq + qg) * DD + h * DH + c * 16;
#pragma unroll
    for (int i = 0; i < 16; i += 4) {
        float4 o4;
        o4.x = acc[i+0]*inv; o4.y = acc[i+1]*inv; o4.z = acc[i+2]*inv; o4.w = acc[i+3]*inv;
        *(float4*)&optr[i] = o4;
    }
}

// ---------------- bias-residual-LayerNorm ----------------
__global__ __launch_bounds__(256) void ln_kernel(
    const float* __restrict__ X, const float* __restrict__ Res,
    const float* __restrict__ g, const float* __restrict__ bb,
    float* __restrict__ out)
{
    __shared__ float red[256];
    const int row = blockIdx.x;
    const int tid = threadIdx.x;
    const size_t base = (size_t)row * DD;

    float v0 = X[base + tid]       + Res[base + tid];
    float v1 = X[base + tid + 256] + Res[base + tid + 256];
    float v2 = X[base + tid + 512] + Res[base + tid + 512];

    red[tid] = v0 + v1 + v2;
    __syncthreads();
    for (int s = 128; s > 0; s >>= 1) {
        if (tid < s) red[tid] += red[tid + s];
        __syncthreads();
    }
    float mean = red[0] * (1.f / DD);
    __syncthreads();

    float d0 = v0 - mean, d1 = v1 - mean, d2 = v2 - mean;
    red[tid] = d0*d0 + d1*d1 + d2*d2;
    __syncthreads();
    for (int s = 128; s > 0; s >>= 1) {
        if (tid < s) red[tid] += red[tid + s];
        __syncthreads();
    }
    float inv = rsqrtf(red[0] * (1.f / DD) + 1e-12f);

    out[base + tid]       = d0 * inv * g[tid]       + bb[tid];
    out[base + tid + 256] = d1 * inv * g[tid + 256] + bb[tid + 256];
    out[base + tid + 512] = d2 * inv * g[tid + 512] + bb[tid + 512];
}

// ---------------- launch ----------------
static void launch_gemm(const float* A, const float* W, const float* bias, float* C,
                        int M, int N, int K, int act)
{
    dim3 grid(N / 128, (M + 127) / 128);
    gemm_tc_kernel<<<grid, 256>>>(A, W, bias, C, M, N, K, act);
}

extern "C" void kernel_launch(void* const* d_in, const int* in_sizes, int n_in,
                              void* d_out, int out_size)
{
    const float* hs      = (const float*)d_in[0];
    const float* tag_emb = (const float*)d_in[1];
    const float* sa_wq = (const float*)d_in[2];  const float* sa_bq = (const float*)d_in[3];
    const float* sa_wk = (const float*)d_in[4];  const float* sa_bk = (const float*)d_in[5];
    const float* sa_wv = (const float*)d_in[6];  const float* sa_bv = (const float*)d_in[7];
    const float* sa_wo = (const float*)d_in[8];  const float* sa_bo = (const float*)d_in[9];
    const float* sa_ln_g = (const float*)d_in[10]; const float* sa_ln_b = (const float*)d_in[11];
    const float* ca_wq = (const float*)d_in[12]; const float* ca_bq = (const float*)d_in[13];
    const float* ca_wk = (const float*)d_in[14]; const float* ca_bk = (const float*)d_in[15];
    const float* ca_wv = (const float*)d_in[16]; const float* ca_bv = (const float*)d_in[17];
    const float* ca_wo = (const float*)d_in[18]; const float* ca_bo = (const float*)d_in[19];
    const float* ca_ln_g = (const float*)d_in[20]; const float* ca_ln_b = (const float*)d_in[21];
    const float* ff_w1 = (const float*)d_in[22]; const float* ff_b1 = (const float*)d_in[23];
    const float* ff_w2 = (const float*)d_in[24]; const float* ff_b2 = (const float*)d_in[25];
    const float* ff_ln_g = (const float*)d_in[26]; const float* ff_ln_b = (const float*)d_in[27];

    float* out = (float*)d_out;

    float *q, *k, *v, *ctx, *t1, *t2, *ff, *tk, *tv;
    cudaGetSymbolAddress((void**)&q,   g_q);
    cudaGetSymbolAddress((void**)&k,   g_k);
    cudaGetSymbolAddress((void**)&v,   g_v);
    cudaGetSymbolAddress((void**)&ctx, g_ctx);
    cudaGetSymbolAddress((void**)&t1,  g_t1);
    cudaGetSymbolAddress((void**)&t2,  g_t2);
    cudaGetSymbolAddress((void**)&ff,  g_ff);
    cudaGetSymbolAddress((void**)&tk,  g_tagk);
    cudaGetSymbolAddress((void**)&tv,  g_tagv);

    const int M = BB * SS;  // 4096

    // ---- self attention ----
    launch_gemm(hs, sa_wq, sa_bq, q, M, DD, DD, 0);
    launch_gemm(hs, sa_wk, sa_bk, k, M, DD, DD, 0);
    launch_gemm(hs, sa_wv, sa_bv, v, M, DD, DD, 0);

    attn_kernel<<<dim3(SS / 64, HH, BB), 256>>>(q, k, v, ctx, SS, SS, (long)SS * DD, RR);

    launch_gemm(ctx, sa_wo, sa_bo, v, M, DD, DD, 0);
    ln_kernel<<<M, 256>>>(v, hs, sa_ln_g, sa_ln_b, t1);

    // ---- cross attention over tag embeddings ----
    launch_gemm(tag_emb, ca_wk, ca_bk, tk, TT, DD, DD, 0);
    launch_gemm(tag_emb, ca_wv, ca_bv, tv, TT, DD, DD, 0);
    launch_gemm(t1, ca_wq, ca_bq, q, M, DD, DD, 0);

    attn_kernel<<<dim3(SS / 64, HH, BB), 256>>>(q, tk, tv, ctx, SS, TT, 0L, -1);

    launch_gemm(ctx, ca_wo, ca_bo, v, M, DD, DD, 0);
    ln_kernel<<<M, 256>>>(v, t1, ca_ln_g, ca_ln_b, t2);

    // ---- FFN ----
    launch_gemm(t2, ff_w1, ff_b1, ff, M, FFD, DD, 1);     // fused exact GELU
    launch_gemm(ff, ff_w2, ff_b2, q, M, DD, FFD, 0);
    ln_kernel<<<M, 256>>>(q, t2, ff_ln_g, ff_ln_b, out);
}

// round 13
// speedup vs baseline: 2.5609x; 1.7261x over previous
#include <cuda_runtime.h>
#include <cuda_bf16.h>
#include <math.h>
#include <stdint.h>

// Problem constants
#define BB 2
#define SS 2048
#define DD 768
#define HH 12
#define DH 64
#define TT 64
#define RR 50
#define FFD 3072

// ---------------- scratch (device globals; no allocation allowed) ----------------
__device__ float g_q  [BB*SS*DD];
__device__ float g_k  [BB*SS*DD];
__device__ float g_v  [BB*SS*DD];
__device__ float g_ctx[BB*SS*DD];
__device__ float g_t1 [BB*SS*DD];
__device__ float g_t2 [BB*SS*DD];
__device__ float g_ff [BB*SS*FFD];
__device__ float g_tagk[TT*DD];
__device__ float g_tagv[TT*DD];

// ================= PTX helpers (portable PTX only: ldmatrix + mma.sync) =================
__device__ __forceinline__ uint32_t smem_u32(const void* p) {
    uint32_t a;
    asm("{ .reg .u64 t; cvta.to.shared.u64 t, %1; cvt.u32.u64 %0, t; }" : "=r"(a) : "l"(p));
    return a;
}
__device__ __forceinline__ void ldsm_x4(uint32_t* r, uint32_t addr) {
    asm volatile("ldmatrix.sync.aligned.m8n8.x4.shared.b16 {%0,%1,%2,%3}, [%4];"
                 : "=r"(r[0]), "=r"(r[1]), "=r"(r[2]), "=r"(r[3]) : "r"(addr));
}
__device__ __forceinline__ void ldsm_x4_t(uint32_t* r, uint32_t addr) {
    asm volatile("ldmatrix.sync.aligned.m8n8.x4.trans.shared.b16 {%0,%1,%2,%3}, [%4];"
                 : "=r"(r[0]), "=r"(r[1]), "=r"(r[2]), "=r"(r[3]) : "r"(addr));
}
__device__ __forceinline__ void mma_bf16(float* d, const uint32_t* a, const uint32_t* b) {
    asm volatile(
        "mma.sync.aligned.m16n8k16.row.col.f32.bf16.bf16.f32 "
        "{%0,%1,%2,%3}, {%4,%5,%6,%7}, {%8,%9}, {%0,%1,%2,%3};"
        : "+f"(d[0]), "+f"(d[1]), "+f"(d[2]), "+f"(d[3])
        : "r"(a[0]), "r"(a[1]), "r"(a[2]), "r"(a[3]), "r"(b[0]), "r"(b[1]));
}

// pack two floats into bf16x2 hi and lo (error) words
__device__ __forceinline__ void split2(float x, float y, uint32_t& hi, uint32_t& lo) {
    __nv_bfloat16 h0 = __float2bfloat16(x);
    __nv_bfloat16 h1 = __float2bfloat16(y);
    __nv_bfloat16 e0 = __float2bfloat16(x - __bfloat162float(h0));
    __nv_bfloat16 e1 = __float2bfloat16(y - __bfloat162float(h1));
    hi = (uint32_t)__bfloat16_as_ushort(h0) | ((uint32_t)__bfloat16_as_ushort(h1) << 16);
    lo = (uint32_t)__bfloat16_as_ushort(e0) | ((uint32_t)__bfloat16_as_ushort(e1) << 16);
}

// ================= HMMA GEMM (validated round 8) =================
#define A_RS 80     // bytes per A smem row
#define B_RS 256    // bytes per B smem row

__global__ __launch_bounds__(256, 2)
void gemm_tc_kernel(const float* __restrict__ A, const float* __restrict__ W,
                    const float* __restrict__ bias, float* __restrict__ C,
                    int M, int N, int K, int act)
{
    __shared__ __align__(16) unsigned char sAhi[128 * A_RS];
    __shared__ __align__(16) unsigned char sAlo[128 * A_RS];
    __shared__ __align__(16) unsigned char sBhi[32 * B_RS];
    __shared__ __align__(16) unsigned char sBlo[32 * B_RS];

    const int tid  = threadIdx.x;
    const int lane = tid & 31;
    const int wid  = tid >> 5;
    const int wm   = (wid & 3) * 32;
    const int wn   = (wid >> 2) * 64;
    const int bm   = blockIdx.y * 128;
    const int bn   = blockIdx.x * 128;

    const uint32_t aHiB = smem_u32(sAhi);
    const uint32_t aLoB = smem_u32(sAlo);
    const uint32_t bHiB = smem_u32(sBhi);
    const uint32_t bLoB = smem_u32(sBlo);

    float acc[2][8][4];
#pragma unroll
    for (int mt = 0; mt < 2; mt++)
#pragma unroll
        for (int nt = 0; nt < 8; nt++)
#pragma unroll
            for (int j = 0; j < 4; j++) acc[mt][nt][j] = 0.f;

    const int a_row = tid >> 1;
    const int a_k   = (tid & 1) * 16;
    const bool a_ok = (bm + a_row) < M;
    const float* ap = A + (size_t)(bm + a_row) * K + a_k;
    const uint32_t a_st = a_row * A_RS + a_k * 2;

    const int b_row = tid >> 3;
    const int b_n4  = (tid & 7) * 4;
    const float* wp = W + (size_t)b_row * N + bn + b_n4;
    const int b_swz_st = (b_row & 7) << 4;

    const uint32_t a_fr = (uint32_t)((wm + (lane & 15)) * A_RS + (lane >> 4) * 16);
    const int b_rb  = (lane & 7) + ((lane >> 3) & 1) * 8;
    const int b_swz = (lane & 7) << 4;
    uint32_t b_col2[4];
#pragma unroll
    for (int p = 0; p < 4; p++)
        b_col2[p] = (uint32_t)(((wn + p * 16 + (lane >> 4) * 8) * 2) ^ b_swz);

    const int nchunks = K >> 5;
    for (int kc = 0; kc < nchunks; kc++) {
        const int k0 = kc << 5;
        __syncthreads();

#pragma unroll
        for (int i = 0; i < 4; i++) {
            float4 v = make_float4(0.f, 0.f, 0.f, 0.f);
            if (a_ok) v = *(const float4*)(ap + k0 + i * 4);
            uint2 hv, lv;
            split2(v.x, v.y, hv.x, lv.x);
            split2(v.z, v.w, hv.y, lv.y);
            uint32_t off = a_st + i * 8;
            *(uint2*)(sAhi + off) = hv;
            *(uint2*)(sAlo + off) = lv;
        }
#pragma unroll
        for (int i = 0; i < 4; i++) {
            float4 v = *(const float4*)(wp + (size_t)k0 * N + i * 32);
            uint2 hv, lv;
            split2(v.x, v.y, hv.x, lv.x);
            split2(v.z, v.w, hv.y, lv.y);
            uint32_t off = b_row * B_RS + ((uint32_t)((b_n4 + i * 32) * 2) ^ b_swz_st);
            *(uint2*)(sBhi + off) = hv;
            *(uint2*)(sBlo + off) = lv;
        }
        __syncthreads();

#pragma unroll
        for (int ks = 0; ks < 2; ks++) {
            const uint32_t klb = ks * 32;
            const uint32_t krb = (ks * 16) * B_RS;

            uint32_t ahi[2][4];
            ldsm_x4(ahi[0], aHiB + a_fr + klb);
            ldsm_x4(ahi[1], aHiB + a_fr + 16 * A_RS + klb);

            uint32_t bf[8][2];
#pragma unroll
            for (int p = 0; p < 4; p++) {
                uint32_t r[4];
                ldsm_x4_t(r, bHiB + krb + (uint32_t)(b_rb * B_RS) + b_col2[p]);
                bf[2*p][0] = r[0]; bf[2*p][1] = r[1];
                bf[2*p+1][0] = r[2]; bf[2*p+1][1] = r[3];
            }
#pragma unroll
            for (int mt = 0; mt < 2; mt++)
#pragma unroll
                for (int nt = 0; nt < 8; nt++)
                    mma_bf16(acc[mt][nt], ahi[mt], bf[nt]);

            uint32_t alo[2][4];
            ldsm_x4(alo[0], aLoB + a_fr + klb);
            ldsm_x4(alo[1], aLoB + a_fr + 16 * A_RS + klb);
#pragma unroll
            for (int mt = 0; mt < 2; mt++)
#pragma unroll
                for (int nt = 0; nt < 8; nt++)
                    mma_bf16(acc[mt][nt], alo[mt], bf[nt]);

#pragma unroll
            for (int p = 0; p < 4; p++) {
                uint32_t r[4];
                ldsm_x4_t(r, bLoB + krb + (uint32_t)(b_rb * B_RS) + b_col2[p]);
                bf[2*p][0] = r[0]; bf[2*p][1] = r[1];
                bf[2*p+1][0] = r[2]; bf[2*p+1][1] = r[3];
            }
#pragma unroll
            for (int mt = 0; mt < 2; mt++)
#pragma unroll
                for (int nt = 0; nt < 8; nt++)
                    mma_bf16(acc[mt][nt], ahi[mt], bf[nt]);
        }
    }

    const int r0 = bm + wm + (lane >> 2);
    const int cbase = bn + wn + (lane & 3) * 2;
#pragma unroll
    for (int mt = 0; mt < 2; mt++) {
#pragma unroll
        for (int half = 0; half < 2; half++) {
            const int row = r0 + mt * 16 + half * 8;
            if (row >= M) continue;
#pragma unroll
            for (int nt = 0; nt < 8; nt++) {
                const int col = cbase + nt * 8;
                float d0 = acc[mt][nt][half * 2 + 0] + bias[col];
                float d1 = acc[mt][nt][half * 2 + 1] + bias[col + 1];
                if (act == 1) {
                    d0 = 0.5f * d0 * (1.f + erff(d0 * 0.70710678118654752440f));
                    d1 = 0.5f * d1 * (1.f + erff(d1 * 0.70710678118654752440f));
                }
                *(float2*)&C[(size_t)row * N + col] = make_float2(d0, d1);
            }
        }
    }
}

// ================= Tensor-core flash attention =================
// Grid: (Sq/128, H, B), 256 threads (8 warps). Each warp owns 16 query rows.
// Key tiles of 64. Q kept as register fragments (hi/lo bf16) for the whole sweep.
// QK^T: 3-term bf16 split; softmax fp32 in registers; PV: 3-term split, P never
// leaves registers (S fragment layout == A fragment layout).
// smem rows: 64 bf16 = 128B, swizzle: byte ^ ((row&7)<<4).
#define AT_QHI 0
#define AT_QLO 16384
#define AT_KHI 32768
#define AT_KLO 40960
#define AT_VHI 49152
#define AT_VLO 57344
#define AT_SMEM 65536

__global__ __launch_bounds__(256, 1)
void attn_tc_kernel(const float* __restrict__ Q, const float* __restrict__ Kg,
                    const float* __restrict__ Vg, float* __restrict__ O,
                    int Sq, int Sk, long kvbs, int bandR)
{
    extern __shared__ __align__(16) unsigned char smem[];
    const uint32_t sbase = smem_u32(smem);
    const int b = blockIdx.z, h = blockIdx.y;
    const int tid  = threadIdx.x;
    const int lane = tid & 31;
    const int wid  = tid >> 5;
    const int wq   = wid * 16;                    // warp's query-row offset in tile
    const int bq   = blockIdx.x * 128;            // CTA query base

    // ---- load Q tile [128 x 64] -> smem bf16 hi/lo (swizzled) ----
    {
        const int qrow = tid >> 1;                // 0..127
        const int d0   = (tid & 1) * 32;          // dim start 0/32
        const float* qp = Q + ((size_t)b * Sq + bq + qrow) * DD + h * DH + d0;
        const int swz = (qrow & 7) << 4;
#pragma unroll
        for (int i = 0; i < 8; i++) {
            float4 v = *(const float4*)(qp + i * 4);
            uint2 hv, lv;
            split2(v.x, v.y, hv.x, lv.x);
            split2(v.z, v.w, hv.y, lv.y);
            uint32_t off = qrow * 128 + ((uint32_t)((d0 + i * 4) * 2) ^ swz);
            *(uint2*)(smem + AT_QHI + off) = hv;
            *(uint2*)(smem + AT_QLO + off) = lv;
        }
    }
    __syncthreads();

    // ---- Q fragments: 4 k-steps x 4 regs, hi + lo ----
    uint32_t qh[4][4], ql[4][4];
    {
        const int row = wq + (lane & 15);
        const int swz = (row & 7) << 4;
        const uint32_t rb = row * 128;
#pragma unroll
        for (int kk = 0; kk < 4; kk++) {
            uint32_t cb = (uint32_t)((kk * 16 + (lane >> 4) * 8) * 2) ^ swz;
            ldsm_x4(qh[kk], sbase + AT_QHI + rb + cb);
            ldsm_x4(ql[kk], sbase + AT_QLO + rb + cb);
        }
    }

    // ---- fragment address components for K (non-trans) and V (trans) ----
    const uint32_t k_row_part = (uint32_t)(((lane & 7) + (lane >> 4) * 8) * 128);
    uint32_t k_dimx[4];
#pragma unroll
    for (int kk = 0; kk < 4; kk++)
        k_dimx[kk] = (uint32_t)((kk * 32 + ((lane >> 3) & 1) * 16)) ^ ((lane & 7) << 4);
    const int v_rb = (lane & 7) + ((lane >> 3) & 1) * 8;
    uint32_t v_col2[4];
#pragma unroll
    for (int p = 0; p < 4; p++)
        v_col2[p] = (uint32_t)(((p * 16 + (lane >> 4) * 8) * 2)) ^ ((lane & 7) << 4);

    // ---- per-row softmax state (each thread: rows rA = wq+(lane>>2), rB = rA+8) ----
    const int qgA = bq + wq + (lane >> 2);
    const int qgB = qgA + 8;
    float mA = -1e30f, mB = -1e30f, lA = 0.f, lB = 0.f;

    float oacc[8][4];
#pragma unroll
    for (int nt = 0; nt < 8; nt++)
#pragma unroll
        for (int j = 0; j < 4; j++) oacc[nt][j] = 0.f;

    const unsigned fm = 0xFFFFFFFFu;

    for (int k0 = 0; k0 < Sk; k0 += 64) {
        __syncthreads();   // previous iteration's ldmatrix reads complete
        // ---- load K/V tile [64 keys x 64 dims] -> smem bf16 hi/lo ----
        {
            const int key = tid >> 2;             // 0..63
            const int d0  = (tid & 3) * 16;       // dims 0/16/32/48
            const size_t gb = (size_t)b * kvbs + (size_t)(k0 + key) * DD + h * DH + d0;
            const int swz = (key & 7) << 4;
#pragma unroll
            for (int i = 0; i < 4; i++) {
                float4 kv = *(const float4*)(Kg + gb + i * 4);
                float4 vv = *(const float4*)(Vg + gb + i * 4);
                uint2 khv, klv, vhv, vlv;
                split2(kv.x, kv.y, khv.x, klv.x);
                split2(kv.z, kv.w, khv.y, klv.y);
                split2(vv.x, vv.y, vhv.x, vlv.x);
                split2(vv.z, vv.w, vhv.y, vlv.y);
                uint32_t off = key * 128 + ((uint32_t)((d0 + i * 4) * 2) ^ swz);
                *(uint2*)(smem + AT_KHI + off) = khv;
                *(uint2*)(smem + AT_KLO + off) = klv;
                *(uint2*)(smem + AT_VHI + off) = vhv;
                *(uint2*)(smem + AT_VLO + off) = vlv;
            }
        }
        __syncthreads();

        // ---- scores S[16 x 64] = Q @ K^T (3-term split) ----
        float sacc[8][4];
#pragma unroll
        for (int nt = 0; nt < 8; nt++)
#pragma unroll
            for (int j = 0; j < 4; j++) sacc[nt][j] = 0.f;

#pragma unroll
        for (int kk = 0; kk < 4; kk++) {
            uint32_t kb[8][2];
#pragma unroll
            for (int j = 0; j < 4; j++) {
                uint32_t r[4];
                ldsm_x4(r, sbase + AT_KHI + (uint32_t)(j * 16 * 128) + k_row_part + k_dimx[kk]);
                kb[2*j][0] = r[0]; kb[2*j][1] = r[1];
                kb[2*j+1][0] = r[2]; kb[2*j+1][1] = r[3];
            }
#pragma unroll
            for (int nt = 0; nt < 8; nt++) mma_bf16(sacc[nt], qh[kk], kb[nt]);
#pragma unroll
            for (int nt = 0; nt < 8; nt++) mma_bf16(sacc[nt], ql[kk], kb[nt]);
#pragma unroll
            for (int j = 0; j < 4; j++) {
                uint32_t r[4];
                ldsm_x4(r, sbase + AT_KLO + (uint32_t)(j * 16 * 128) + k_row_part + k_dimx[kk]);
                kb[2*j][0] = r[0]; kb[2*j][1] = r[1];
                kb[2*j+1][0] = r[2]; kb[2*j+1][1] = r[3];
            }
#pragma unroll
            for (int nt = 0; nt < 8; nt++) mma_bf16(sacc[nt], qh[kk], kb[nt]);
        }

        // ---- scale + band mask + online softmax ----
        float mxA = -1e30f, mxB = -1e30f;
#pragma unroll
        for (int nt = 0; nt < 8; nt++) {
            const int colb = k0 + nt * 8 + ((lane & 3) << 1);
#pragma unroll
            for (int d = 0; d < 2; d++) {
                int col = colb + d;
                int dA = qgA - col; if (dA < 0) dA = -dA;
                int dB = qgB - col; if (dB < 0) dB = -dB;
                float sA = sacc[nt][d]     * 0.125f + ((dA <= bandR) ? 1.f : 0.f);
                float sB = sacc[nt][d + 2] * 0.125f + ((dB <= bandR) ? 1.f : 0.f);
                sacc[nt][d]     = sA;
                sacc[nt][d + 2] = sB;
                mxA = fmaxf(mxA, sA);
                mxB = fmaxf(mxB, sB);
            }
        }
        mxA = fmaxf(mxA, __shfl_xor_sync(fm, mxA, 1));
        mxA = fmaxf(mxA, __shfl_xor_sync(fm, mxA, 2));
        mxB = fmaxf(mxB, __shfl_xor_sync(fm, mxB, 1));
        mxB = fmaxf(mxB, __shfl_xor_sync(fm, mxB, 2));

        const float mAn = fmaxf(mA, mxA);
        const float mBn = fmaxf(mB, mxB);
        const float scA = __expf(mA - mAn);
        const float scB = __expf(mB - mBn);
        mA = mAn; mB = mBn;

        float smA = 0.f, smB = 0.f;
#pragma unroll
        for (int nt = 0; nt < 8; nt++) {
            float p0 = __expf(sacc[nt][0] - mAn);
            float p1 = __expf(sacc[nt][1] - mAn);
            float p2 = __expf(sacc[nt][2] - mBn);
            float p3 = __expf(sacc[nt][3] - mBn);
            sacc[nt][0] = p0; sacc[nt][1] = p1; sacc[nt][2] = p2; sacc[nt][3] = p3;
            smA += p0 + p1;
            smB += p2 + p3;
        }
        smA += __shfl_xor_sync(fm, smA, 1);
        smA += __shfl_xor_sync(fm, smA, 2);
        smB += __shfl_xor_sync(fm, smB, 1);
        smB += __shfl_xor_sync(fm, smB, 2);
        lA = lA * scA + smA;
        lB = lB * scB + smB;

#pragma unroll
        for (int nt = 0; nt < 8; nt++) {
            oacc[nt][0] *= scA; oacc[nt][1] *= scA;
            oacc[nt][2] *= scB; oacc[nt][3] *= scB;
        }

        // ---- PV: O += P @ V (3-term split; P stays in registers) ----
#pragma unroll
        for (int kk = 0; kk < 4; kk++) {
            uint32_t ph[4], pl[4];
            split2(sacc[2*kk][0],   sacc[2*kk][1],   ph[0], pl[0]);
            split2(sacc[2*kk][2],   sacc[2*kk][3],   ph[1], pl[1]);
            split2(sacc[2*kk+1][0], sacc[2*kk+1][1], ph[2], pl[2]);
            split2(sacc[2*kk+1][2], sacc[2*kk+1][3], ph[3], pl[3]);

            const uint32_t vrow = (uint32_t)((kk * 16 + v_rb) * 128);
            uint32_t vb[8][2];
#pragma unroll
            for (int p = 0; p < 4; p++) {
                uint32_t r[4];
                ldsm_x4_t(r, sbase + AT_VHI + vrow + v_col2[p]);
                vb[2*p][0] = r[0]; vb[2*p][1] = r[1];
                vb[2*p+1][0] = r[2]; vb[2*p+1][1] = r[3];
            }
#pragma unroll
            for (int nt = 0; nt < 8; nt++) mma_bf16(oacc[nt], ph, vb[nt]);
#pragma unroll
            for (int nt = 0; nt < 8; nt++) mma_bf16(oacc[nt], pl, vb[nt]);
#pragma unroll
            for (int p = 0; p < 4; p++) {
                uint32_t r[4];
                ldsm_x4_t(r, sbase + AT_VLO + vrow + v_col2[p]);
                vb[2*p][0] = r[0]; vb[2*p][1] = r[1];
                vb[2*p+1][0] = r[2]; vb[2*p+1][1] = r[3];
            }
#pragma unroll
            for (int nt = 0; nt < 8; nt++) mma_bf16(oacc[nt], ph, vb[nt]);
        }
    }

    // ---- write O (normalize by l) ----
    const float invA = 1.f / lA;
    const float invB = 1.f / lB;
    float* oA = O + ((size_t)b * Sq + qgA) * DD + h * DH + (lane & 3) * 2;
    float* oB = O + ((size_t)b * Sq + qgB) * DD + h * DH + (lane & 3) * 2;
#pragma unroll
    for (int nt = 0; nt < 8; nt++) {
        *(float2*)(oA + nt * 8) = make_float2(oacc[nt][0] * invA, oacc[nt][1] * invA);
        *(float2*)(oB + nt * 8) = make_float2(oacc[nt][2] * invB, oacc[nt][3] * invB);
    }
}

// ---------------- bias-residual-LayerNorm ----------------
__global__ __launch_bounds__(256) void ln_kernel(
    const float* __restrict__ X, const float* __restrict__ Res,
    const float* __restrict__ g, const float* __restrict__ bb,
    float* __restrict__ out)
{
    __shared__ float red[256];
    const int row = blockIdx.x;
    const int tid = threadIdx.x;
    const size_t base = (size_t)row * DD;

    float v0 = X[base + tid]       + Res[base + tid];
    float v1 = X[base + tid + 256] + Res[base + tid + 256];
    float v2 = X[base + tid + 512] + Res[base + tid + 512];

    red[tid] = v0 + v1 + v2;
    __syncthreads();
    for (int s = 128; s > 0; s >>= 1) {
        if (tid < s) red[tid] += red[tid + s];
        __syncthreads();
    }
    float mean = red[0] * (1.f / DD);
    __syncthreads();

    float d0 = v0 - mean, d1 = v1 - mean, d2 = v2 - mean;
    red[tid] = d0*d0 + d1*d1 + d2*d2;
    __syncthreads();
    for (int s = 128; s > 0; s >>= 1) {
        if (tid < s) red[tid] += red[tid + s];
        __syncthreads();
    }
    float inv = rsqrtf(red[0] * (1.f / DD) + 1e-12f);

    out[base + tid]       = d0 * inv * g[tid]       + bb[tid];
    out[base + tid + 256] = d1 * inv * g[tid + 256] + bb[tid + 256];
    out[base + tid + 512] = d2 * inv * g[tid + 512] + bb[tid + 512];
}

// ---------------- launch ----------------
static void launch_gemm(const float* A, const float* W, const float* bias, float* C,
                        int M, int N, int K, int act)
{
    dim3 grid(N / 128, (M + 127) / 128);
    gemm_tc_kernel<<<grid, 256>>>(A, W, bias, C, M, N, K, act);
}

extern "C" void kernel_launch(void* const* d_in, const int* in_sizes, int n_in,
                              void* d_out, int out_size)
{
    const float* hs      = (const float*)d_in[0];
    const float* tag_emb = (const float*)d_in[1];
    const float* sa_wq = (const float*)d_in[2];  const float* sa_bq = (const float*)d_in[3];
    const float* sa_wk = (const float*)d_in[4];  const float* sa_bk = (const float*)d_in[5];
    const float* sa_wv = (const float*)d_in[6];  const float* sa_bv = (const float*)d_in[7];
    const float* sa_wo = (const float*)d_in[8];  const float* sa_bo = (const float*)d_in[9];
    const float* sa_ln_g = (const float*)d_in[10]; const float* sa_ln_b = (const float*)d_in[11];
    const float* ca_wq = (const float*)d_in[12]; const float* ca_bq = (const float*)d_in[13];
    const float* ca_wk = (const float*)d_in[14]; const float* ca_bk = (const float*)d_in[15];
    const float* ca_wv = (const float*)d_in[16]; const float* ca_bv = (const float*)d_in[17];
    const float* ca_wo = (const float*)d_in[18]; const float* ca_bo = (const float*)d_in[19];
    const float* ca_ln_g = (const float*)d_in[20]; const float* ca_ln_b = (const float*)d_in[21];
    const float* ff_w1 = (const float*)d_in[22]; const float* ff_b1 = (const float*)d_in[23];
    const float* ff_w2 = (const float*)d_in[24]; const float* ff_b2 = (const float*)d_in[25];
    const float* ff_ln_g = (const float*)d_in[26]; const float* ff_ln_b = (const float*)d_in[27];

    float* out = (float*)d_out;

    cudaFuncSetAttribute(attn_tc_kernel, cudaFuncAttributeMaxDynamicSharedMemorySize,
                         AT_SMEM);

    float *q, *k, *v, *ctx, *t1, *t2, *ff, *tk, *tv;
    cudaGetSymbolAddress((void**)&q,   g_q);
    cudaGetSymbolAddress((void**)&k,   g_k);
    cudaGetSymbolAddress((void**)&v,   g_v);
    cudaGetSymbolAddress((void**)&ctx, g_ctx);
    cudaGetSymbolAddress((void**)&t1,  g_t1);
    cudaGetSymbolAddress((void**)&t2,  g_t2);
    cudaGetSymbolAddress((void**)&ff,  g_ff);
    cudaGetSymbolAddress((void**)&tk,  g_tagk);
    cudaGetSymbolAddress((void**)&tv,  g_tagv);

    const int M = BB * SS;  // 4096

    // ---- self attention ----
    launch_gemm(hs, sa_wq, sa_bq, q, M, DD, DD, 0);
    launch_gemm(hs, sa_wk, sa_bk, k, M, DD, DD, 0);
    launch_gemm(hs, sa_wv, sa_bv, v, M, DD, DD, 0);

    attn_tc_kernel<<<dim3(SS / 128, HH, BB), 256, AT_SMEM>>>(
        q, k, v, ctx, SS, SS, (long)SS * DD, RR);

    launch_gemm(ctx, sa_wo, sa_bo, v, M, DD, DD, 0);
    ln_kernel<<<M, 256>>>(v, hs, sa_ln_g, sa_ln_b, t1);

    // ---- cross attention over tag embeddings ----
    launch_gemm(tag_emb, ca_wk, ca_bk, tk, TT, DD, DD, 0);
    launch_gemm(tag_emb, ca_wv, ca_bv, tv, TT, DD, DD, 0);
    launch_gemm(t1, ca_wq, ca_bq, q, M, DD, DD, 0);

    attn_tc_kernel<<<dim3(SS / 128, HH, BB), 256, AT_SMEM>>>(
        q, tk, tv, ctx, SS, TT, 0L, -1);

    launch_gemm(ctx, ca_wo, ca_bo, v, M, DD, DD, 0);
    ln_kernel<<<M, 256>>>(v, t1, ca_ln_g, ca_ln_b, t2);

    // ---- FFN ----
    launch_gemm(t2, ff_w1, ff_b1, ff, M, FFD, DD, 1);     // fused exact GELU
    launch_gemm(ff, ff_w2, ff_b2, q, M, DD, FFD, 0);
    ln_kernel<<<M, 256>>>(q, t2, ff_ln_g, ff_ln_b, out);
}